// round 7
// baseline (speedup 1.0000x reference)
#include <cuda_runtime.h>
#include <math.h>

#define NN 2048
#define TT 5
#define DD 64
#define TOPK 21
#define BB 32
#define EPS 1e-5f
#define NEG_SLOPE 0.2f
#define BN_PAIRS (BB*NN)        // 65536
#define ATTN_BLOCKS 1024
#define FULLMASK 0xffffffffu

// ---------------- scratch (static device globals; no allocation allowed) ----
__device__ float g_cos[NN*NN];          // 16 MB cosine matrix
__device__ float g_inv[NN];             // 1/||emb_i||
__device__ float g_es_emb[NN];          // emb_n . a_src[D:2D]
__device__ float g_ed_emb[NN];          // emb_n . a_dst[D:2D]
__device__ int   g_nbr[NN*TOPK];        // top-k neighbor indices
__device__ float g_h[BN_PAIRS*DD];      // 16 MB  h[b,n,d]
__device__ float g_esrc[BN_PAIRS];
__device__ float g_edst[BN_PAIRS];
__device__ float g_outpre[BN_PAIRS*DD]; // 16 MB  z*emb before BN
__device__ float g_part[ATTN_BLOCKS*2*DD]; // per-block BN partials (deterministic)
__device__ float g_scale[DD];
__device__ float g_shift[DD];

// ---------------- 1. per-node precompute: inv-norm, emb-half attention dots --
__global__ void k_node_pre(const float* __restrict__ emb,
                           const float* __restrict__ a_src,
                           const float* __restrict__ a_dst) {
    __shared__ float sm[4][2][3];
    int g = threadIdx.x >> 6;          // 4 nodes per block
    int l = threadIdx.x & 63;          // channel
    int n = blockIdx.x * 4 + g;
    float v  = emb[n*DD + l];
    float s0 = v * v;
    float s1 = v * a_src[DD + l];
    float s2 = v * a_dst[DD + l];
    #pragma unroll
    for (int s = 16; s > 0; s >>= 1) {
        s0 += __shfl_down_sync(FULLMASK, s0, s);
        s1 += __shfl_down_sync(FULLMASK, s1, s);
        s2 += __shfl_down_sync(FULLMASK, s2, s);
    }
    int w = l >> 5;
    if ((l & 31) == 0) { sm[g][w][0] = s0; sm[g][w][1] = s1; sm[g][w][2] = s2; }
    __syncthreads();
    if (l == 0) {
        g_inv[n]    = rsqrtf(sm[g][0][0] + sm[g][1][0]);
        g_es_emb[n] = sm[g][0][1] + sm[g][1][1];
        g_ed_emb[n] = sm[g][0][2] + sm[g][1][2];
    }
}

// ---------------- 2. cosine matrix: 32x32 tiles, K=64 in smem, vector I/O ---
__global__ void k_cos(const float* __restrict__ emb) {
    __shared__ float As[32][DD];
    __shared__ float Bs[32][DD];
    int tx = threadIdx.x & 15, ty = threadIdx.x >> 4;   // 16x16
    int bi = blockIdx.y * 32, bj = blockIdx.x * 32;
    // 32 rows x 64 floats = 512 float4; 256 threads -> 2 each
    {
        const float4* ea = (const float4*)(emb + (size_t)bi * DD);
        const float4* eb = (const float4*)(emb + (size_t)bj * DD);
        float4* sa = (float4*)&As[0][0];
        float4* sb = (float4*)&Bs[0][0];
        sa[threadIdx.x]       = ea[threadIdx.x];
        sa[threadIdx.x + 256] = ea[threadIdx.x + 256];
        sb[threadIdx.x]       = eb[threadIdx.x];
        sb[threadIdx.x + 256] = eb[threadIdx.x + 256];
    }
    __syncthreads();
    int r0 = 2*ty, r1 = 2*ty + 1, q0 = 2*tx, q1 = 2*tx + 1;
    float c00 = 0.f, c01 = 0.f, c10 = 0.f, c11 = 0.f;
    #pragma unroll
    for (int k = 0; k < DD; k++) {
        float a0 = As[r0][k], a1 = As[r1][k];
        float b0 = Bs[q0][k], b1 = Bs[q1][k];
        c00 += a0*b0; c01 += a0*b1; c10 += a1*b0; c11 += a1*b1;
    }
    float i0 = g_inv[bi+r0], i1 = g_inv[bi+r1];
    float j0 = g_inv[bj+q0], j1 = g_inv[bj+q1];
    ((float2*)(g_cos + (size_t)(bi+r0)*NN + bj))[tx] = make_float2(c00*i0*j0, c01*i0*j1);
    ((float2*)(g_cos + (size_t)(bi+r1)*NN + bj))[tx] = make_float2(c10*i1*j0, c11*i1*j1);
}

// ---------------- 3. top-21 per row: warp-shfl argmax, low-index tie-break --
__global__ void k_topk() {
    __shared__ float vals[NN];       // 8 KB
    __shared__ float wv[8];
    __shared__ int   wi[8];
    int i = blockIdx.x;
    int lane = threadIdx.x & 31, warp = threadIdx.x >> 5;
    // vectorized row load: 2048 floats = 512 float4, 256 threads -> 2 each
    {
        const float4* row4 = (const float4*)(g_cos + (size_t)i * NN);
        float4* v4 = (float4*)vals;
        v4[threadIdx.x]       = row4[threadIdx.x];
        v4[threadIdx.x + 256] = row4[threadIdx.x + 256];
    }
    __syncthreads();
    for (int k = 0; k < TOPK; k++) {
        float bv = -INFINITY; int bidx = 0;
        #pragma unroll
        for (int s = 0; s < NN/256; s++) {
            int j = threadIdx.x + s*256;
            float v = vals[j];
            if (v > bv) { bv = v; bidx = j; }   // ascending j -> lowest index on tie
        }
        #pragma unroll
        for (int s = 16; s > 0; s >>= 1) {
            float ov = __shfl_down_sync(FULLMASK, bv, s);
            int   oi = __shfl_down_sync(FULLMASK, bidx, s);
            if (ov > bv || (ov == bv && oi < bidx)) { bv = ov; bidx = oi; }
        }
        if (lane == 0) { wv[warp] = bv; wi[warp] = bidx; }
        __syncthreads();
        if (threadIdx.x == 0) {
            float fv = wv[0]; int fi = wi[0];
            #pragma unroll
            for (int w = 1; w < 8; w++) {
                float ov = wv[w]; int oi = wi[w];
                if (ov > fv || (ov == fv && oi < fi)) { fv = ov; fi = oi; }
            }
            g_nbr[i*TOPK + k] = fi;
            vals[fi] = -INFINITY;
        }
        __syncthreads();
    }
}

// ---------------- 4. h = x.W^T + Wb ; e_src/e_dst ---------------------------
__global__ void k_h(const float* __restrict__ x,  const float* __restrict__ W,
                    const float* __restrict__ Wb, const float* __restrict__ a_src,
                    const float* __restrict__ a_dst) {
    __shared__ float sm[4][2][2];
    int g = threadIdx.x >> 6;
    int l = threadIdx.x & 63;        // d
    int p = blockIdx.x * 4 + g;      // (b,n) flat
    int n = p & (NN - 1);
    const float* xp = x + (size_t)p * TT;
    float h = Wb[l];
    #pragma unroll
    for (int t = 0; t < TT; t++) h += xp[t] * W[l*TT + t];
    g_h[(size_t)p*DD + l] = h;
    float vs = h * a_src[l];
    float vd = h * a_dst[l];
    #pragma unroll
    for (int s = 16; s > 0; s >>= 1) {
        vs += __shfl_down_sync(FULLMASK, vs, s);
        vd += __shfl_down_sync(FULLMASK, vd, s);
    }
    int w = l >> 5;
    if ((l & 31) == 0) { sm[g][w][0] = vs; sm[g][w][1] = vd; }
    __syncthreads();
    if (l == 0) {
        g_esrc[p] = sm[g][0][0] + sm[g][1][0] + g_es_emb[n];
        g_edst[p] = sm[g][0][1] + sm[g][1][1] + g_ed_emb[n];
    }
}

// ---------------- 5. attention: softmax + aggregate, same-batch 2-pair ILP --
// lane handles channels (2*lane, 2*lane+1); warp handles pairs (2w, 2w+1)
__global__ void __launch_bounds__(256) k_attn(const float* __restrict__ emb) {
    int warpG = blockIdx.x * 8 + (threadIdx.x >> 5);
    int lane  = threadIdx.x & 31;
    const int totalWarps = ATTN_BLOCKS * 8;             // 8192 -> 8 pairs/warp
    float s0 = 0.f, q0 = 0.f, s1 = 0.f, q1 = 0.f;
    // pairs (2*warpG, 2*warpG+1), stride 2*totalWarps: 4 iterations, no tail
    for (int p = 2*warpG; p < BN_PAIRS; p += 2*totalWarps) {
        int pA = p, pB = p + 1;                         // same batch b
        int bA = pA >> 11, iA = pA & (NN-1);
        int bB = pB >> 11, iB = pB & (NN-1);
        float esA = g_esrc[pA], esB = g_esrc[pB];
        int jnA = 0, jnB = 0;
        float lrA = -INFINITY, lrB = -INFINITY;
        if (lane < TOPK) {
            jnA = g_nbr[iA*TOPK + lane];
            jnB = g_nbr[iB*TOPK + lane];
            float tA = esA + g_edst[(bA << 11) + jnA];
            float tB = esB + g_edst[(bB << 11) + jnB];
            lrA = tA > 0.f ? tA : NEG_SLOPE * tA;
            lrB = tB > 0.f ? tB : NEG_SLOPE * tB;
        }
        float mxA = lrA, mxB = lrB;
        #pragma unroll
        for (int s = 16; s > 0; s >>= 1) {
            mxA = fmaxf(mxA, __shfl_xor_sync(FULLMASK, mxA, s));
            mxB = fmaxf(mxB, __shfl_xor_sync(FULLMASK, mxB, s));
        }
        float exA = (lane < TOPK) ? expf(lrA - mxA) : 0.f;
        float exB = (lane < TOPK) ? expf(lrB - mxB) : 0.f;
        float smA = exA, smB = exB;
        #pragma unroll
        for (int s = 16; s > 0; s >>= 1) {
            smA += __shfl_xor_sync(FULLMASK, smA, s);
            smB += __shfl_xor_sync(FULLMASK, smB, s);
        }
        float alA = exA / smA, alB = exB / smB;
        float a0 = 0.f, a1 = 0.f, b0 = 0.f, b1 = 0.f;
        #pragma unroll
        for (int k = 0; k < TOPK; k++) {
            float akA = __shfl_sync(FULLMASK, alA, k);
            int   jkA = __shfl_sync(FULLMASK, jnA, k);
            float akB = __shfl_sync(FULLMASK, alB, k);
            int   jkB = __shfl_sync(FULLMASK, jnB, k);
            const float2* hpA = (const float2*)(g_h + ((size_t)((bA << 11) + jkA) << 6));
            const float2* hpB = (const float2*)(g_h + ((size_t)((bB << 11) + jkB) << 6));
            float2 vA = hpA[lane];
            float2 vB = hpB[lane];
            a0 += akA * vA.x;  a1 += akA * vA.y;
            b0 += akB * vB.x;  b1 += akB * vB.y;
        }
        float2 eA = ((const float2*)(emb + (iA << 6)))[lane];
        float2 eB = ((const float2*)(emb + (iB << 6)))[lane];
        float oA0 = fmaxf(a0, 0.f) * eA.x;
        float oA1 = fmaxf(a1, 0.f) * eA.y;
        float oB0 = fmaxf(b0, 0.f) * eB.x;
        float oB1 = fmaxf(b1, 0.f) * eB.y;
        ((float2*)(g_outpre + ((size_t)pA << 6)))[lane] = make_float2(oA0, oA1);
        ((float2*)(g_outpre + ((size_t)pB << 6)))[lane] = make_float2(oB0, oB1);
        s0 += oA0 + oB0; q0 += oA0*oA0 + oB0*oB0;
        s1 += oA1 + oB1; q1 += oA1*oA1 + oB1*oB1;
    }
    // BN partials: this lane's sums belong to channels 2*lane and 2*lane+1
    __shared__ float bsum[8*DD], bsq[8*DD];
    int w = threadIdx.x >> 5;
    bsum[w*DD + 2*lane]     = s0;  bsum[w*DD + 2*lane + 1] = s1;
    bsq [w*DD + 2*lane]     = q0;  bsq [w*DD + 2*lane + 1] = q1;
    __syncthreads();
    if (threadIdx.x < DD) {
        float S = 0.f, Q = 0.f;
        #pragma unroll
        for (int ww = 0; ww < 8; ww++) { S += bsum[ww*DD + threadIdx.x]; Q += bsq[ww*DD + threadIdx.x]; }
        g_part[blockIdx.x*2*DD + threadIdx.x]      = S;
        g_part[blockIdx.x*2*DD + DD + threadIdx.x] = Q;
    }
}

// ---------------- 6. BN stats -> scale/shift (deterministic serial reduce) --
__global__ void k_stats(const float* __restrict__ gamma, const float* __restrict__ beta) {
    int c = threadIdx.x;   // 64 threads
    float S = 0.f, Q = 0.f;
    for (int pb = 0; pb < ATTN_BLOCKS; pb++) {
        S += g_part[pb*2*DD + c];
        Q += g_part[pb*2*DD + DD + c];
    }
    const float invM = 1.0f / (float)BN_PAIRS;
    float mean = S * invM;
    float var  = Q * invM - mean * mean;
    float sc = gamma[c] * rsqrtf(var + EPS);
    g_scale[c] = sc;
    g_shift[c] = beta[c] - mean * sc;
}

// ---------------- 7. BN apply + relu + fc (float2) ---------------------------
__global__ void __launch_bounds__(256) k_final(const float* __restrict__ fc_w,
                                               const float* __restrict__ fc_b,
                                               float* __restrict__ out) {
    int warpG = blockIdx.x * 8 + (threadIdx.x >> 5);
    int lane  = threadIdx.x & 31;
    const int totalWarps = 512 * 8;
    float sc0 = g_scale[2*lane],     sh0 = g_shift[2*lane];
    float sc1 = g_scale[2*lane + 1], sh1 = g_shift[2*lane + 1];
    float f0 = fc_w[2*lane], f1 = fc_w[2*lane + 1], fb = fc_b[0];
    for (int p = warpG; p < BN_PAIRS; p += totalWarps) {
        float2 o = ((const float2*)(g_outpre + ((size_t)p << 6)))[lane];
        float v = fmaxf(o.x * sc0 + sh0, 0.f) * f0
                + fmaxf(o.y * sc1 + sh1, 0.f) * f1;
        #pragma unroll
        for (int s = 16; s > 0; s >>= 1) v += __shfl_down_sync(FULLMASK, v, s);
        if (lane == 0) out[p] = v + fb;
    }
}

extern "C" void kernel_launch(void* const* d_in, const int* in_sizes, int n_in,
                              void* d_out, int out_size) {
    const float* x     = (const float*)d_in[0];   // [B,N,T]
    const float* emb   = (const float*)d_in[1];   // [N,D]
    const float* W     = (const float*)d_in[2];   // [D,T]
    const float* Wb    = (const float*)d_in[3];   // [D]
    const float* a_src = (const float*)d_in[4];   // [2D]
    const float* a_dst = (const float*)d_in[5];   // [2D]
    const float* gamma = (const float*)d_in[6];   // [D]
    const float* beta  = (const float*)d_in[7];   // [D]
    const float* fc_w  = (const float*)d_in[8];   // [1,D]
    const float* fc_b  = (const float*)d_in[9];   // [1]
    float* out = (float*)d_out;                   // [B*N]

    k_node_pre<<<NN/4, 256>>>(emb, a_src, a_dst);
    k_cos<<<dim3(NN/32, NN/32), 256>>>(emb);
    k_topk<<<NN, 256>>>();
    k_h<<<BN_PAIRS/4, 256>>>(x, W, Wb, a_src, a_dst);
    k_attn<<<ATTN_BLOCKS, 256>>>(emb);
    k_stats<<<1, DD>>>(gamma, beta);
    k_final<<<512, 256>>>(fc_w, fc_b, out);
}

// round 9
// speedup vs baseline: 1.9742x; 1.9742x over previous
#include <cuda_runtime.h>
#include <math.h>

#define NN 2048
#define TT 5
#define DD 64
#define TOPK 21
#define BB 32
#define EPS 1e-5f
#define NEG_SLOPE 0.2f
#define BN_PAIRS (BB*NN)        // 65536
#define ATTN_BLOCKS 1024
#define FULLMASK 0xffffffffu

// ---------------- scratch (static device globals; no allocation allowed) ----
__device__ float g_cos[NN*NN];          // 16 MB cosine matrix
__device__ float g_inv[NN];             // 1/||emb_i||
__device__ float g_es_emb[NN];          // emb_n . a_src[D:2D]
__device__ float g_ed_emb[NN];          // emb_n . a_dst[D:2D]
__device__ int   g_nbr[NN*TOPK];        // top-k neighbor indices
__device__ float g_h[BN_PAIRS*DD];      // 16 MB  h[b,n,d]
__device__ float g_esrc[BN_PAIRS];
__device__ float g_edst[BN_PAIRS];
__device__ float g_outpre[BN_PAIRS*DD]; // 16 MB  z*emb before BN
__device__ float g_part[ATTN_BLOCKS*2*DD]; // per-block BN partials (deterministic)
__device__ float g_scale[DD];
__device__ float g_shift[DD];

// ---------------- 1. per-node precompute: inv-norm, emb-half attention dots --
__global__ void k_node_pre(const float* __restrict__ emb,
                           const float* __restrict__ a_src,
                           const float* __restrict__ a_dst) {
    __shared__ float sm[4][2][3];
    int g = threadIdx.x >> 6;          // 4 nodes per block
    int l = threadIdx.x & 63;          // channel
    int n = blockIdx.x * 4 + g;
    float v  = emb[n*DD + l];
    float s0 = v * v;
    float s1 = v * a_src[DD + l];
    float s2 = v * a_dst[DD + l];
    #pragma unroll
    for (int s = 16; s > 0; s >>= 1) {
        s0 += __shfl_down_sync(FULLMASK, s0, s);
        s1 += __shfl_down_sync(FULLMASK, s1, s);
        s2 += __shfl_down_sync(FULLMASK, s2, s);
    }
    int w = l >> 5;
    if ((l & 31) == 0) { sm[g][w][0] = s0; sm[g][w][1] = s1; sm[g][w][2] = s2; }
    __syncthreads();
    if (l == 0) {
        g_inv[n]    = rsqrtf(sm[g][0][0] + sm[g][1][0]);
        g_es_emb[n] = sm[g][0][1] + sm[g][1][1];
        g_ed_emb[n] = sm[g][0][2] + sm[g][1][2];
    }
}

// ---------------- 2. cosine matrix: 32x32 tiles, float4 k-groups ------------
// Tiles stored as 17 float4 per row (68-float pitch). Thread (tx,ty) computes
// rows (ty, ty+16) x cols (tx, tx+16): row-stride 4 banks + lane-major tx
// -> 2-way max on the LDS.128 -> byte-optimal crossbar use.
__global__ void k_cos(const float* __restrict__ emb) {
    __shared__ float4 As4[32*17];
    __shared__ float4 Bs4[32*17];
    int tx = threadIdx.x & 15, ty = threadIdx.x >> 4;   // 16x16
    int bi = blockIdx.y * 32, bj = blockIdx.x * 32;
    // fill: 32 rows x 16 float4 per tile
    for (int e = threadIdx.x; e < 32*16; e += 256) {
        int r = e >> 4, c4 = e & 15;
        As4[r*17 + c4] = ((const float4*)(emb + (size_t)(bi + r)*DD))[c4];
        Bs4[r*17 + c4] = ((const float4*)(emb + (size_t)(bj + r)*DD))[c4];
    }
    __syncthreads();
    int r0 = ty, r1 = ty + 16, q0 = tx, q1 = tx + 16;
    float c00 = 0.f, c01 = 0.f, c10 = 0.f, c11 = 0.f;
    #pragma unroll
    for (int k4 = 0; k4 < 16; k4++) {
        float4 a0 = As4[r0*17 + k4];
        float4 a1 = As4[r1*17 + k4];
        float4 b0 = Bs4[q0*17 + k4];
        float4 b1 = Bs4[q1*17 + k4];
        c00 += a0.x*b0.x + a0.y*b0.y + a0.z*b0.z + a0.w*b0.w;
        c01 += a0.x*b1.x + a0.y*b1.y + a0.z*b1.z + a0.w*b1.w;
        c10 += a1.x*b0.x + a1.y*b0.y + a1.z*b0.z + a1.w*b0.w;
        c11 += a1.x*b1.x + a1.y*b1.y + a1.z*b1.z + a1.w*b1.w;
    }
    float i0 = g_inv[bi+r0], i1 = g_inv[bi+r1];
    float j0 = g_inv[bj+q0], j1 = g_inv[bj+q1];
    g_cos[(size_t)(bi+r0)*NN + bj+q0] = c00*i0*j0;
    g_cos[(size_t)(bi+r0)*NN + bj+q1] = c01*i0*j1;
    g_cos[(size_t)(bi+r1)*NN + bj+q0] = c10*i1*j0;
    g_cos[(size_t)(bi+r1)*NN + bj+q1] = c11*i1*j1;
}

// ---------------- 3. top-21 per row: warp-shfl argmax, low-index tie-break --
__global__ void k_topk() {
    __shared__ float vals[NN];       // 8 KB
    __shared__ float wv[8];
    __shared__ int   wi[8];
    int i = blockIdx.x;
    int lane = threadIdx.x & 31, warp = threadIdx.x >> 5;
    {
        const float4* row4 = (const float4*)(g_cos + (size_t)i * NN);
        float4* v4 = (float4*)vals;
        v4[threadIdx.x]       = row4[threadIdx.x];
        v4[threadIdx.x + 256] = row4[threadIdx.x + 256];
    }
    __syncthreads();
    for (int k = 0; k < TOPK; k++) {
        float bv = -INFINITY; int bidx = 0;
        #pragma unroll
        for (int s = 0; s < NN/256; s++) {
            int j = threadIdx.x + s*256;
            float v = vals[j];
            if (v > bv) { bv = v; bidx = j; }   // ascending j -> lowest index on tie
        }
        #pragma unroll
        for (int s = 16; s > 0; s >>= 1) {
            float ov = __shfl_down_sync(FULLMASK, bv, s);
            int   oi = __shfl_down_sync(FULLMASK, bidx, s);
            if (ov > bv || (ov == bv && oi < bidx)) { bv = ov; bidx = oi; }
        }
        if (lane == 0) { wv[warp] = bv; wi[warp] = bidx; }
        __syncthreads();
        if (threadIdx.x == 0) {
            float fv = wv[0]; int fi = wi[0];
            #pragma unroll
            for (int w = 1; w < 8; w++) {
                float ov = wv[w]; int oi = wi[w];
                if (ov > fv || (ov == fv && oi < fi)) { fv = ov; fi = oi; }
            }
            g_nbr[i*TOPK + k] = fi;
            vals[fi] = -INFINITY;
        }
        __syncthreads();
    }
}

// ---------------- 4. h = x.W^T + Wb ; e_src/e_dst  (thread-per-pair) --------
__global__ void __launch_bounds__(128) k_h(const float* __restrict__ x,
                                           const float* __restrict__ W,
                                           const float* __restrict__ Wb,
                                           const float* __restrict__ a_src,
                                           const float* __restrict__ a_dst) {
    __shared__ float sWt[TT*DD];      // sWt[t*DD + d] = W[d*TT + t]
    __shared__ float sWb[DD], sAs[DD], sAd[DD];
    int tid = threadIdx.x;
    for (int i = tid; i < TT*DD; i += 128) {
        int d = i / TT, t = i % TT;
        sWt[t*DD + d] = W[i];
    }
    for (int i = tid; i < DD; i += 128) {
        sWb[i] = Wb[i]; sAs[i] = a_src[i]; sAd[i] = a_dst[i];
    }
    __syncthreads();
    int p = blockIdx.x * 128 + tid;   // 512 blocks x 128 = 65536 pairs, 1 each
    int n = p & (NN - 1);
    float xv[TT];
    #pragma unroll
    for (int t = 0; t < TT; t++) xv[t] = x[(size_t)p*TT + t];
    float es = 0.f, ed = 0.f;
    float4* out4 = (float4*)(g_h + ((size_t)p << 6));
    #pragma unroll
    for (int d4 = 0; d4 < 16; d4++) {
        float4 h = ((const float4*)sWb)[d4];
        #pragma unroll
        for (int t = 0; t < TT; t++) {
            float4 w = ((const float4*)(sWt + t*DD))[d4];
            h.x += xv[t]*w.x; h.y += xv[t]*w.y; h.z += xv[t]*w.z; h.w += xv[t]*w.w;
        }
        out4[d4] = h;
        float4 as = ((const float4*)sAs)[d4];
        float4 ad = ((const float4*)sAd)[d4];
        es += h.x*as.x + h.y*as.y + h.z*as.z + h.w*as.w;
        ed += h.x*ad.x + h.y*ad.y + h.z*ad.z + h.w*ad.w;
    }
    g_esrc[p] = es + g_es_emb[n];
    g_edst[p] = ed + g_ed_emb[n];
}

// ---------------- 5. attention: softmax + aggregate, same-batch 2-pair ILP --
// lane handles channels (2*lane, 2*lane+1); warp handles pairs (2w, 2w+1)
__global__ void __launch_bounds__(256) k_attn(const float* __restrict__ emb) {
    int warpG = blockIdx.x * 8 + (threadIdx.x >> 5);
    int lane  = threadIdx.x & 31;
    const int totalWarps = ATTN_BLOCKS * 8;             // 8192 -> 8 pairs/warp
    float s0 = 0.f, q0 = 0.f, s1 = 0.f, q1 = 0.f;
    for (int p = 2*warpG; p < BN_PAIRS; p += 2*totalWarps) {
        int pA = p, pB = p + 1;                         // same batch b
        int bA = pA >> 11, iA = pA & (NN-1);
        int bB = pB >> 11, iB = pB & (NN-1);
        float esA = g_esrc[pA], esB = g_esrc[pB];
        int jnA = 0, jnB = 0;
        float lrA = -INFINITY, lrB = -INFINITY;
        if (lane < TOPK) {
            jnA = g_nbr[iA*TOPK + lane];
            jnB = g_nbr[iB*TOPK + lane];
            float tA = esA + g_edst[(bA << 11) + jnA];
            float tB = esB + g_edst[(bB << 11) + jnB];
            lrA = tA > 0.f ? tA : NEG_SLOPE * tA;
            lrB = tB > 0.f ? tB : NEG_SLOPE * tB;
        }
        float mxA = lrA, mxB = lrB;
        #pragma unroll
        for (int s = 16; s > 0; s >>= 1) {
            mxA = fmaxf(mxA, __shfl_xor_sync(FULLMASK, mxA, s));
            mxB = fmaxf(mxB, __shfl_xor_sync(FULLMASK, mxB, s));
        }
        float exA = (lane < TOPK) ? expf(lrA - mxA) : 0.f;
        float exB = (lane < TOPK) ? expf(lrB - mxB) : 0.f;
        float smA = exA, smB = exB;
        #pragma unroll
        for (int s = 16; s > 0; s >>= 1) {
            smA += __shfl_xor_sync(FULLMASK, smA, s);
            smB += __shfl_xor_sync(FULLMASK, smB, s);
        }
        float alA = exA / smA, alB = exB / smB;
        float a0 = 0.f, a1 = 0.f, b0 = 0.f, b1 = 0.f;
        #pragma unroll
        for (int k = 0; k < TOPK; k++) {
            float akA = __shfl_sync(FULLMASK, alA, k);
            int   jkA = __shfl_sync(FULLMASK, jnA, k);
            float akB = __shfl_sync(FULLMASK, alB, k);
            int   jkB = __shfl_sync(FULLMASK, jnB, k);
            const float2* hpA = (const float2*)(g_h + ((size_t)((bA << 11) + jkA) << 6));
            const float2* hpB = (const float2*)(g_h + ((size_t)((bB << 11) + jkB) << 6));
            float2 vA = hpA[lane];
            float2 vB = hpB[lane];
            a0 += akA * vA.x;  a1 += akA * vA.y;
            b0 += akB * vB.x;  b1 += akB * vB.y;
        }
        float2 eA = ((const float2*)(emb + (iA << 6)))[lane];
        float2 eB = ((const float2*)(emb + (iB << 6)))[lane];
        float oA0 = fmaxf(a0, 0.f) * eA.x;
        float oA1 = fmaxf(a1, 0.f) * eA.y;
        float oB0 = fmaxf(b0, 0.f) * eB.x;
        float oB1 = fmaxf(b1, 0.f) * eB.y;
        ((float2*)(g_outpre + ((size_t)pA << 6)))[lane] = make_float2(oA0, oA1);
        ((float2*)(g_outpre + ((size_t)pB << 6)))[lane] = make_float2(oB0, oB1);
        s0 += oA0 + oB0; q0 += oA0*oA0 + oB0*oB0;
        s1 += oA1 + oB1; q1 += oA1*oA1 + oB1*oB1;
    }
    // BN partials: this lane's sums belong to channels 2*lane and 2*lane+1
    __shared__ float bsum[8*DD], bsq[8*DD];
    int w = threadIdx.x >> 5;
    bsum[w*DD + 2*lane]     = s0;  bsum[w*DD + 2*lane + 1] = s1;
    bsq [w*DD + 2*lane]     = q0;  bsq [w*DD + 2*lane + 1] = q1;
    __syncthreads();
    if (threadIdx.x < DD) {
        float S = 0.f, Q = 0.f;
        #pragma unroll
        for (int ww = 0; ww < 8; ww++) { S += bsum[ww*DD + threadIdx.x]; Q += bsq[ww*DD + threadIdx.x]; }
        g_part[blockIdx.x*2*DD + threadIdx.x]      = S;
        g_part[blockIdx.x*2*DD + DD + threadIdx.x] = Q;
    }
}

// ---------------- 6. BN stats -> scale/shift (parallel, deterministic) ------
__global__ void k_stats(const float* __restrict__ gamma, const float* __restrict__ beta) {
    __shared__ float red[1024];
    int slot = threadIdx.x & 127;
    int g    = threadIdx.x >> 7;    // 0..7
    float S = 0.f;
    for (int pb = g; pb < ATTN_BLOCKS; pb += 8)
        S += g_part[pb*128 + slot];
    red[threadIdx.x] = S;
    __syncthreads();
    if (threadIdx.x < 128) {
        float T = 0.f;
        #pragma unroll
        for (int gg = 0; gg < 8; gg++) T += red[gg*128 + threadIdx.x];
        red[threadIdx.x] = T;
    }
    __syncthreads();
    if (threadIdx.x < DD) {
        int c = threadIdx.x;
        const float invM = 1.0f / (float)BN_PAIRS;
        float mean = red[c] * invM;
        float var  = red[DD + c] * invM - mean * mean;
        float sc = gamma[c] * rsqrtf(var + EPS);
        g_scale[c] = sc;
        g_shift[c] = beta[c] - mean * sc;
    }
}

// ---------------- 7. BN apply + relu + fc (float2) ---------------------------
__global__ void __launch_bounds__(256) k_final(const float* __restrict__ fc_w,
                                               const float* __restrict__ fc_b,
                                               float* __restrict__ out) {
    int warpG = blockIdx.x * 8 + (threadIdx.x >> 5);
    int lane  = threadIdx.x & 31;
    const int totalWarps = 512 * 8;
    float sc0 = g_scale[2*lane],     sh0 = g_shift[2*lane];
    float sc1 = g_scale[2*lane + 1], sh1 = g_shift[2*lane + 1];
    float f0 = fc_w[2*lane], f1 = fc_w[2*lane + 1], fb = fc_b[0];
    for (int p = warpG; p < BN_PAIRS; p += totalWarps) {
        float2 o = ((const float2*)(g_outpre + ((size_t)p << 6)))[lane];
        float v = fmaxf(o.x * sc0 + sh0, 0.f) * f0
                + fmaxf(o.y * sc1 + sh1, 0.f) * f1;
        #pragma unroll
        for (int s = 16; s > 0; s >>= 1) v += __shfl_down_sync(FULLMASK, v, s);
        if (lane == 0) out[p] = v + fb;
    }
}

extern "C" void kernel_launch(void* const* d_in, const int* in_sizes, int n_in,
                              void* d_out, int out_size) {
    const float* x     = (const float*)d_in[0];   // [B,N,T]
    const float* emb   = (const float*)d_in[1];   // [N,D]
    const float* W     = (const float*)d_in[2];   // [D,T]
    const float* Wb    = (const float*)d_in[3];   // [D]
    const float* a_src = (const float*)d_in[4];   // [2D]
    const float* a_dst = (const float*)d_in[5];   // [2D]
    const float* gamma = (const float*)d_in[6];   // [D]
    const float* beta  = (const float*)d_in[7];   // [D]
    const float* fc_w  = (const float*)d_in[8];   // [1,D]
    const float* fc_b  = (const float*)d_in[9];   // [1]
    float* out = (float*)d_out;                   // [B*N]

    k_node_pre<<<NN/4, 256>>>(emb, a_src, a_dst);
    k_cos<<<dim3(NN/32, NN/32), 256>>>(emb);
    k_topk<<<NN, 256>>>();
    k_h<<<BN_PAIRS/128, 128>>>(x, W, Wb, a_src, a_dst);
    k_attn<<<ATTN_BLOCKS, 256>>>(emb);
    k_stats<<<1, 1024>>>(gamma, beta);
    k_final<<<512, 256>>>(fc_w, fc_b, out);
}